// round 1
// baseline (speedup 1.0000x reference)
#include <cuda_runtime.h>
#include <math.h>

#define NMAX 50000
#define EMAX 500000

// ---------------- scratch (static device globals; no allocations) ----------------
__device__ float g_hu1[NMAX * 128];
__device__ float g_hi1[NMAX * 128];
__device__ float g_fs [NMAX * 128];
__device__ float g_el [NMAX * 4];
__device__ float g_er [NMAX * 4];
__device__ float g_e  [EMAX * 4];
__device__ float g_wl [512];
__device__ float g_wr [512];
__device__ float g_wae[64];
__device__ int   g_indptr_ui[NMAX + 1];
__device__ int   g_indptr_iu[NMAX + 1];
__device__ int   g_eid_ui[EMAX];
__device__ int   g_eid_iu[EMAX];
__device__ int   g_cnt[NMAX];
__device__ int   g_cursor[NMAX];

// ---------------- tiny utility kernels ----------------
__global__ void fill_int_kernel(int* p, int v, int n) {
    int i = blockIdx.x * blockDim.x + threadIdx.x;
    if (i < n) p[i] = v;
}
__global__ void copy_int_kernel(int* dst, const int* src, int n) {
    int i = blockIdx.x * blockDim.x + threadIdx.x;
    if (i < n) dst[i] = src[i];
}
__global__ void hist_kernel(const int* __restrict__ d, int* cnt, int E) {
    int i = blockIdx.x * blockDim.x + threadIdx.x;
    if (i < E) atomicAdd(&cnt[d[i]], 1);
}
// single-block chunked exclusive scan: indptr[0]=0, indptr[i+1]=sum cnt[0..i]
__global__ void scan_kernel(const int* __restrict__ cnt, int* __restrict__ indptr, int n) {
    __shared__ int carry;
    __shared__ int warp_sums[32];
    int tid = threadIdx.x;
    int lane = tid & 31, warp = tid >> 5;
    if (tid == 0) { carry = 0; indptr[0] = 0; }
    __syncthreads();
    for (int base = 0; base < n; base += 1024) {
        int i = base + tid;
        int v = (i < n) ? cnt[i] : 0;
        int x = v;
        #pragma unroll
        for (int o = 1; o < 32; o <<= 1) {
            int y = __shfl_up_sync(0xffffffffu, x, o);
            if (lane >= o) x += y;
        }
        if (lane == 31) warp_sums[warp] = x;
        __syncthreads();
        if (warp == 0) {
            int s = warp_sums[lane];
            #pragma unroll
            for (int o = 1; o < 32; o <<= 1) {
                int y = __shfl_up_sync(0xffffffffu, s, o);
                if (lane >= o) s += y;
            }
            warp_sums[lane] = s;
        }
        __syncthreads();
        int incl = x + (warp > 0 ? warp_sums[warp - 1] : 0) + carry;
        if (i < n) indptr[i + 1] = incl;
        __syncthreads();
        if (tid == 1023) carry = incl;
        __syncthreads();
    }
}
__global__ void scatter_kernel(const int* __restrict__ d, int* cursor, int* eid, int E) {
    int i = blockIdx.x * blockDim.x + threadIdx.x;
    if (i < E) {
        int p = atomicAdd(&cursor[d[i]], 1);
        eid[p] = i;
    }
}

// ---------------- reduced attention weights ----------------
// out[f*4+h] = sum_d W[f*128 + h*32 + d] * a[h*32 + d]
__global__ void reduce_weight_kernel(const float* __restrict__ W, const float* __restrict__ a,
                                     float* __restrict__ out, int rows) {
    int f = blockIdx.x * blockDim.x + threadIdx.x;
    if (f >= rows) return;
    #pragma unroll
    for (int h = 0; h < 4; h++) {
        float s = 0.f;
        #pragma unroll
        for (int d = 0; d < 32; d++) s = fmaf(W[f * 128 + h * 32 + d], a[h * 32 + d], s);
        out[f * 4 + h] = s;
    }
}

// y[n,h] = sum_f x[n,f] * Wred[f*4+h]   (one warp per row)
__global__ __launch_bounds__(128) void attn_proj_kernel(const float* __restrict__ X,
                                                        const float* __restrict__ Wred,
                                                        float* __restrict__ out, int N) {
    __shared__ float w[512];
    int tid = threadIdx.x;
    #pragma unroll
    for (int i = tid; i < 512; i += 128) w[i] = Wred[i];
    __syncthreads();
    int warp = tid >> 5, lane = tid & 31;
    int n = blockIdx.x * 4 + warp;
    if (n >= N) return;
    float a0 = 0.f, a1 = 0.f, a2 = 0.f, a3 = 0.f;
    #pragma unroll
    for (int r = 0; r < 4; r++) {
        int f = lane + r * 32;
        float x = X[(size_t)n * 128 + f];
        a0 = fmaf(x, w[f * 4 + 0], a0);
        a1 = fmaf(x, w[f * 4 + 1], a1);
        a2 = fmaf(x, w[f * 4 + 2], a2);
        a3 = fmaf(x, w[f * 4 + 3], a3);
    }
    #pragma unroll
    for (int o = 16; o; o >>= 1) {
        a0 += __shfl_down_sync(0xffffffffu, a0, o);
        a1 += __shfl_down_sync(0xffffffffu, a1, o);
        a2 += __shfl_down_sync(0xffffffffu, a2, o);
        a3 += __shfl_down_sync(0xffffffffu, a3, o);
    }
    if (lane == 0) {
        out[n * 4 + 0] = a0; out[n * 4 + 1] = a1;
        out[n * 4 + 2] = a2; out[n * 4 + 3] = a3;
    }
}

// ---------------- fs = A[M,128] @ B[128,128]  (fp32 SGEMM, 128x128 tile) ----------------
__global__ __launch_bounds__(256, 2) void sgemm128_kernel(const float* __restrict__ A,
                                                          const float* __restrict__ B,
                                                          float* __restrict__ C, int M) {
    __shared__ float As[16][128];
    __shared__ float Bs[16][128];
    const int tid = threadIdx.x;
    const int tx = tid & 15, ty = tid >> 4;
    const int m0 = blockIdx.x * 128;
    float acc[8][8];
    #pragma unroll
    for (int i = 0; i < 8; i++)
        #pragma unroll
        for (int j = 0; j < 8; j++) acc[i][j] = 0.f;

    for (int k0 = 0; k0 < 128; k0 += 16) {
        #pragma unroll
        for (int r = 0; r < 2; r++) {
            int q = tid + r * 256;
            int row = q >> 2;
            int c = (q & 3) * 4;
            float4 v = make_float4(0.f, 0.f, 0.f, 0.f);
            int gr = m0 + row;
            if (gr < M) v = *reinterpret_cast<const float4*>(A + (size_t)gr * 128 + k0 + c);
            As[c + 0][row] = v.x; As[c + 1][row] = v.y;
            As[c + 2][row] = v.z; As[c + 3][row] = v.w;
        }
        #pragma unroll
        for (int r = 0; r < 2; r++) {
            int q = tid + r * 256;
            int row = q >> 5;
            int c = (q & 31) * 4;
            *reinterpret_cast<float4*>(&Bs[row][c]) =
                *reinterpret_cast<const float4*>(B + (size_t)(k0 + row) * 128 + c);
        }
        __syncthreads();
        #pragma unroll
        for (int k = 0; k < 16; k++) {
            float4 a0 = *reinterpret_cast<const float4*>(&As[k][ty * 8]);
            float4 a1 = *reinterpret_cast<const float4*>(&As[k][ty * 8 + 4]);
            float4 b0 = *reinterpret_cast<const float4*>(&Bs[k][tx * 8]);
            float4 b1 = *reinterpret_cast<const float4*>(&Bs[k][tx * 8 + 4]);
            float ra[8] = {a0.x, a0.y, a0.z, a0.w, a1.x, a1.y, a1.z, a1.w};
            float rb[8] = {b0.x, b0.y, b0.z, b0.w, b1.x, b1.y, b1.z, b1.w};
            #pragma unroll
            for (int i = 0; i < 8; i++)
                #pragma unroll
                for (int j = 0; j < 8; j++) acc[i][j] = fmaf(ra[i], rb[j], acc[i][j]);
        }
        __syncthreads();
    }
    #pragma unroll
    for (int i = 0; i < 8; i++) {
        int gr = m0 + ty * 8 + i;
        if (gr < M) {
            #pragma unroll
            for (int j = 0; j < 8; j += 4) {
                float4 v = make_float4(acc[i][j], acc[i][j + 1], acc[i][j + 2], acc[i][j + 3]);
                *reinterpret_cast<float4*>(C + (size_t)gr * 128 + tx * 8 + j) = v;
            }
        }
    }
}

// ---------------- per-edge attention logits ----------------
// e[edge,h] = leaky_relu(el[src,h] + er[dst,h] + Ef[edge,:16] @ Wae[:,h], 0.2)
__global__ __launch_bounds__(128) void edge_score_kernel(const float* __restrict__ Ef,
                                                         const int* __restrict__ src,
                                                         const int* __restrict__ dst,
                                                         const float* __restrict__ el,
                                                         const float* __restrict__ er,
                                                         const float* __restrict__ Wae,
                                                         float* __restrict__ eo, int E) {
    __shared__ float w[64];
    if (threadIdx.x < 64) w[threadIdx.x] = Wae[threadIdx.x];
    __syncthreads();
    int e = blockIdx.x * blockDim.x + threadIdx.x;
    if (e >= E) return;
    int s = src[e], d = dst[e];
    const float4* efp = reinterpret_cast<const float4*>(Ef + (size_t)e * 16);
    float4 v0 = efp[0], v1 = efp[1], v2 = efp[2], v3 = efp[3];
    float ef[16] = {v0.x, v0.y, v0.z, v0.w, v1.x, v1.y, v1.z, v1.w,
                    v2.x, v2.y, v2.z, v2.w, v3.x, v3.y, v3.z, v3.w};
    #pragma unroll
    for (int h = 0; h < 4; h++) {
        float acc = el[s * 4 + h] + er[d * 4 + h];
        #pragma unroll
        for (int f = 0; f < 16; f++) acc = fmaf(ef[f], w[f * 4 + h], acc);
        eo[(size_t)e * 4 + h] = acc > 0.f ? acc : 0.2f * acc;
    }
}

// ---------------- gather-based softmax aggregation (one block per dst node) ----------------
__global__ __launch_bounds__(128) void aggregate_kernel(const int* __restrict__ indptr,
                                                        const int* __restrict__ eid,
                                                        const int* __restrict__ src,
                                                        const float* __restrict__ e,
                                                        const float* __restrict__ fs,
                                                        float* __restrict__ out,
                                                        int N, int do_relu) {
    __shared__ int   s_src[128];
    __shared__ float s_e[128 * 4];
    int n = blockIdx.x;
    int beg = indptr[n], end = indptr[n + 1];
    int t = threadIdx.x;
    int h = t >> 5;
    float mh = -1e30f, sh = 0.f, acc = 0.f;
    for (int cs = beg; cs < end; cs += 128) {
        int cnt = min(128, end - cs);
        __shared__ int s_eid[128];
        if (t < cnt) {
            int ei = eid[cs + t];
            s_eid[t] = ei;
            s_src[t] = src[ei];
        }
        __syncthreads();
        for (int q = t; q < cnt * 4; q += 128)
            s_e[q] = e[(size_t)s_eid[q >> 2] * 4 + (q & 3)];
        __syncthreads();
        float cm = mh;
        for (int j = 0; j < cnt; j++) cm = fmaxf(cm, s_e[j * 4 + h]);
        float scale = __expf(mh - cm);  // 0 on first chunk (mh = -1e30)
        acc *= scale;
        sh  *= scale;
        mh = cm;
        for (int j = 0; j < cnt; j++) {
            float wv = __expf(s_e[j * 4 + h] - mh);
            sh += wv;
            acc = fmaf(wv, fs[(size_t)s_src[j] * 128 + t], acc);
        }
        __syncthreads();
    }
    float o = acc / (sh + 1e-9f);
    if (do_relu) o = fmaxf(o, 0.f);
    out[(size_t)n * 128 + t] = o;
}

// ---------------- host-side orchestration ----------------
static void build_csr(const int* dst, int E, int N, int* indptr, int* eid,
                      int* cnt, int* cursor) {
    fill_int_kernel<<<(N + 255) / 256, 256>>>(cnt, 0, N);
    hist_kernel<<<(E + 255) / 256, 256>>>(dst, cnt, E);
    scan_kernel<<<1, 1024>>>(cnt, indptr, N);
    copy_int_kernel<<<(N + 255) / 256, 256>>>(cursor, indptr, N);
    scatter_kernel<<<(E + 255) / 256, 256>>>(dst, cursor, eid, E);
}

static void run_edge_gat(const float* h_src, const float* h_dst, const float* Ef,
                         const int* src, const int* dst,
                         const float* W, const float* We,
                         const float* al, const float* ar, const float* ae,
                         const int* indptr, const int* eid,
                         float* wl, float* wr, float* wae,
                         float* el, float* er, float* e_buf, float* fs,
                         float* out, int Ns, int Nd, int E, int relu_flag) {
    reduce_weight_kernel<<<1, 128>>>(W, al, wl, 128);
    reduce_weight_kernel<<<1, 128>>>(W, ar, wr, 128);
    reduce_weight_kernel<<<1, 128>>>(We, ae, wae, 16);
    attn_proj_kernel<<<(Ns + 3) / 4, 128>>>(h_src, wl, el, Ns);
    attn_proj_kernel<<<(Nd + 3) / 4, 128>>>(h_dst, wr, er, Nd);
    sgemm128_kernel<<<(Ns + 127) / 128, 256>>>(h_src, W, fs, Ns);
    edge_score_kernel<<<(E + 127) / 128, 128>>>(Ef, src, dst, el, er, wae, e_buf, E);
    aggregate_kernel<<<Nd, 128>>>(indptr, eid, src, e_buf, fs, out, Nd, relu_flag);
}

extern "C" void kernel_launch(void* const* d_in, const int* in_sizes, int n_in,
                              void* d_out, int out_size) {
    const float* X_user = (const float*)d_in[0];
    const float* X_item = (const float*)d_in[1];
    const float* Ef_ui0 = (const float*)d_in[2];
    const float* Ef_iu0 = (const float*)d_in[3];
    const float* Ef_ui1 = (const float*)d_in[4];
    const float* Ef_iu1 = (const float*)d_in[5];
    // weight groups: g=0:ui0, 1:iu0, 2:ui1, 3:iu1 ; within: W, We, al, ar, ae
    const float* Wt[4][5];
    for (int g = 0; g < 4; g++)
        for (int k = 0; k < 5; k++)
            Wt[g][k] = (const float*)d_in[6 + g * 5 + k];
    const int* src_ui = (const int*)d_in[26];
    const int* dst_ui = (const int*)d_in[27];
    const int* src_iu = (const int*)d_in[28];
    const int* dst_iu = (const int*)d_in[29];

    const int NU = in_sizes[0] / 128;
    const int NI = in_sizes[1] / 128;
    const int E_ui = in_sizes[26];
    const int E_iu = in_sizes[28];

    float *hu1, *hi1, *fs, *el, *er, *e_buf, *wl, *wr, *wae;
    int *ip_ui, *ip_iu, *eid_ui, *eid_iu, *cnt, *cur;
    cudaGetSymbolAddress((void**)&hu1, g_hu1);
    cudaGetSymbolAddress((void**)&hi1, g_hi1);
    cudaGetSymbolAddress((void**)&fs, g_fs);
    cudaGetSymbolAddress((void**)&el, g_el);
    cudaGetSymbolAddress((void**)&er, g_er);
    cudaGetSymbolAddress((void**)&e_buf, g_e);
    cudaGetSymbolAddress((void**)&wl, g_wl);
    cudaGetSymbolAddress((void**)&wr, g_wr);
    cudaGetSymbolAddress((void**)&wae, g_wae);
    cudaGetSymbolAddress((void**)&ip_ui, g_indptr_ui);
    cudaGetSymbolAddress((void**)&ip_iu, g_indptr_iu);
    cudaGetSymbolAddress((void**)&eid_ui, g_eid_ui);
    cudaGetSymbolAddress((void**)&eid_iu, g_eid_iu);
    cudaGetSymbolAddress((void**)&cnt, g_cnt);
    cudaGetSymbolAddress((void**)&cur, g_cursor);

    float* out_hu2 = (float*)d_out;                      // [NU,128]
    float* out_hi2 = (float*)d_out + (size_t)NU * 128;   // [NI,128]

    // CSR by destination, reused across both layers (edge lists identical)
    build_csr(dst_ui, E_ui, NI, ip_ui, eid_ui, cnt, cur);
    build_csr(dst_iu, E_iu, NU, ip_iu, eid_iu, cnt, cur);

    // ---- layer 0 ----
    // hi1 = edge_gat(X_user -> X_item), relu
    run_edge_gat(X_user, X_item, Ef_ui0, src_ui, dst_ui,
                 Wt[0][0], Wt[0][1], Wt[0][2], Wt[0][3], Wt[0][4],
                 ip_ui, eid_ui, wl, wr, wae, el, er, e_buf, fs,
                 hi1, NU, NI, E_ui, 1);
    // hu1 = edge_gat(X_item -> X_user), relu
    run_edge_gat(X_item, X_user, Ef_iu0, src_iu, dst_iu,
                 Wt[1][0], Wt[1][1], Wt[1][2], Wt[1][3], Wt[1][4],
                 ip_iu, eid_iu, wl, wr, wae, el, er, e_buf, fs,
                 hu1, NI, NU, E_iu, 1);

    // ---- layer 1 ----
    // hi2 = edge_gat(hu1 -> hi1)
    run_edge_gat(hu1, hi1, Ef_ui1, src_ui, dst_ui,
                 Wt[2][0], Wt[2][1], Wt[2][2], Wt[2][3], Wt[2][4],
                 ip_ui, eid_ui, wl, wr, wae, el, er, e_buf, fs,
                 out_hi2, NU, NI, E_ui, 0);
    // hu2 = edge_gat(hi1 -> hu1)
    run_edge_gat(hi1, hu1, Ef_iu1, src_iu, dst_iu,
                 Wt[3][0], Wt[3][1], Wt[3][2], Wt[3][3], Wt[3][4],
                 ip_iu, eid_iu, wl, wr, wae, el, er, e_buf, fs,
                 out_hu2, NI, NU, E_iu, 0);
}

// round 2
// speedup vs baseline: 1.3259x; 1.3259x over previous
#include <cuda_runtime.h>
#include <math.h>
#include <stdint.h>

#define NMAX 50000
#define EMAX 500000

// ---------------- scratch (static device globals) ----------------
__device__ float g_hu1[NMAX * 128];
__device__ float g_hi1[NMAX * 128];
__device__ float g_fs [NMAX * 128];
__device__ float g_el_ui[NMAX * 4];
__device__ float g_er_ui[NMAX * 4];
__device__ float g_el_iu[NMAX * 4];
__device__ float g_er_iu[NMAX * 4];
__device__ float g_w  [EMAX * 4];
__device__ float g_wl [4][512];
__device__ float g_wr [4][512];
__device__ float g_wae[4][64];
__device__ int   g_ip_ui[NMAX + 1];
__device__ int   g_ip_iu[NMAX + 1];
__device__ int   g_pos_ui[EMAX];
__device__ int   g_pos_iu[EMAX];
__device__ int   g_srcp_ui[EMAX];
__device__ int   g_srcp_iu[EMAX];
__device__ int   g_cnt[NMAX];
__device__ int   g_cur[NMAX];

// ---------------- small utility kernels ----------------
__global__ void fill_int_kernel(int* p, int v, int n) {
    int i = blockIdx.x * blockDim.x + threadIdx.x;
    if (i < n) p[i] = v;
}
__global__ void copy_int_kernel(int* dst, const int* src, int n) {
    int i = blockIdx.x * blockDim.x + threadIdx.x;
    if (i < n) dst[i] = src[i];
}
__global__ void hist_kernel(const int* __restrict__ d, int* cnt, int E) {
    int i = blockIdx.x * blockDim.x + threadIdx.x;
    if (i < E) atomicAdd(&cnt[d[i]], 1);
}
// single-block chunked exclusive scan
__global__ void scan_kernel(const int* __restrict__ cnt, int* __restrict__ indptr, int n) {
    __shared__ int carry;
    __shared__ int warp_sums[32];
    int tid = threadIdx.x;
    int lane = tid & 31, warp = tid >> 5;
    if (tid == 0) { carry = 0; indptr[0] = 0; }
    __syncthreads();
    for (int base = 0; base < n; base += 1024) {
        int i = base + tid;
        int x = (i < n) ? cnt[i] : 0;
        #pragma unroll
        for (int o = 1; o < 32; o <<= 1) {
            int y = __shfl_up_sync(0xffffffffu, x, o);
            if (lane >= o) x += y;
        }
        if (lane == 31) warp_sums[warp] = x;
        __syncthreads();
        if (warp == 0) {
            int s = warp_sums[lane];
            #pragma unroll
            for (int o = 1; o < 32; o <<= 1) {
                int y = __shfl_up_sync(0xffffffffu, s, o);
                if (lane >= o) s += y;
            }
            warp_sums[lane] = s;
        }
        __syncthreads();
        int incl = x + (warp > 0 ? warp_sums[warp - 1] : 0) + carry;
        if (i < n) indptr[i + 1] = incl;
        __syncthreads();
        if (tid == 1023) carry = incl;
        __syncthreads();
    }
}
// scatter: compute CSR position for each edge, and src permuted into CSR order
__global__ void scatter_kernel(const int* __restrict__ d, const int* __restrict__ s,
                               int* cursor, int* pos, int* srcp, int E) {
    int i = blockIdx.x * blockDim.x + threadIdx.x;
    if (i < E) {
        int p = atomicAdd(&cursor[d[i]], 1);
        pos[i] = p;
        srcp[p] = s[i];
    }
}

// ---------------- reduced attention weights (all 4 groups, one launch) ----------------
struct RW {
    const float* W[4];  const float* We[4];
    const float* al[4]; const float* ar[4]; const float* ae[4];
    float* wl; float* wr; float* wae;
};
// wl[g][f*4+h] = sum_d W[f*128 + h*32 + d] * al[h*32+d]   (likewise wr, wae)
__global__ void reduce_all_kernel(RW p) {
    int g = blockIdx.x / 3;
    int which = blockIdx.x % 3;
    int f = threadIdx.x;
    if (which == 2) {
        if (f >= 16) return;
        const float* We = p.We[g];
        const float* ae = p.ae[g];
        #pragma unroll
        for (int h = 0; h < 4; h++) {
            float s = 0.f;
            #pragma unroll
            for (int d = 0; d < 32; d++) s = fmaf(We[f * 128 + h * 32 + d], ae[h * 32 + d], s);
            p.wae[g * 64 + f * 4 + h] = s;
        }
    } else {
        const float* W = p.W[g];
        const float* a = which ? p.ar[g] : p.al[g];
        float* o = (which ? p.wr : p.wl) + g * 512;
        #pragma unroll
        for (int h = 0; h < 4; h++) {
            float s = 0.f;
            #pragma unroll
            for (int d = 0; d < 32; d++) s = fmaf(W[f * 128 + h * 32 + d], a[h * 32 + d], s);
            o[f * 4 + h] = s;
        }
    }
}

// ---------------- dual attention projection: outA = X@wA, outB = X@wB ----------------
__global__ __launch_bounds__(128) void attn_proj2_kernel(const float* __restrict__ X,
                                                         const float* __restrict__ wA,
                                                         const float* __restrict__ wB,
                                                         float* __restrict__ outA,
                                                         float* __restrict__ outB, int N) {
    __shared__ float wa[512], wb[512];
    int tid = threadIdx.x;
    #pragma unroll
    for (int i = tid; i < 512; i += 128) { wa[i] = wA[i]; wb[i] = wB[i]; }
    __syncthreads();
    int warp = tid >> 5, lane = tid & 31;
    int n = blockIdx.x * 4 + warp;
    if (n >= N) return;
    float a[4] = {0, 0, 0, 0}, b[4] = {0, 0, 0, 0};
    #pragma unroll
    for (int r = 0; r < 4; r++) {
        int f = lane + r * 32;
        float x = X[(size_t)n * 128 + f];
        #pragma unroll
        for (int h = 0; h < 4; h++) {
            a[h] = fmaf(x, wa[f * 4 + h], a[h]);
            b[h] = fmaf(x, wb[f * 4 + h], b[h]);
        }
    }
    #pragma unroll
    for (int o = 16; o; o >>= 1)
        #pragma unroll
        for (int h = 0; h < 4; h++) {
            a[h] += __shfl_down_sync(0xffffffffu, a[h], o);
            b[h] += __shfl_down_sync(0xffffffffu, b[h], o);
        }
    if (lane == 0) {
        #pragma unroll
        for (int h = 0; h < 4; h++) { outA[n * 4 + h] = a[h]; outB[n * 4 + h] = b[h]; }
    }
}

// ---------------- 3xTF32 tensor-core GEMM: C[M,128] = A[M,128] @ B[128,128] ----------------
__device__ __forceinline__ float f2tf32(float x) {
    uint32_t u;
    asm("cvt.rna.tf32.f32 %0, %1;" : "=r"(u) : "f"(x));
    return __uint_as_float(u);
}
__device__ __forceinline__ void mma_tf32(float* d, const uint32_t* a, const uint32_t* b) {
    asm volatile("mma.sync.aligned.m16n8k8.row.col.f32.tf32.tf32.f32 "
                 "{%0,%1,%2,%3}, {%4,%5,%6,%7}, {%8,%9}, {%0,%1,%2,%3};\n"
                 : "+f"(d[0]), "+f"(d[1]), "+f"(d[2]), "+f"(d[3])
                 : "r"(a[0]), "r"(a[1]), "r"(a[2]), "r"(a[3]), "r"(b[0]), "r"(b[1]));
}

__global__ __launch_bounds__(256, 2) void gemm3t_kernel(const float* __restrict__ A,
                                                        const float* __restrict__ B,
                                                        float* __restrict__ C, int M) {
    __shared__ float As[2][128][20];   // [hi/lo][m][k16] pad->20
    __shared__ float Bs[2][16][136];   // [hi/lo][k16][n128] pad->136
    const int tid = threadIdx.x;
    const int lane = tid & 31, wid = tid >> 5;
    const int wm = wid & 3, wn = wid >> 2;      // warps 4 (m) x 2 (n)
    const int m0 = blockIdx.x * 128;
    const int r = lane >> 2, c = lane & 3;

    float acc[2][8][4];
    #pragma unroll
    for (int i = 0; i < 2; i++)
        #pragma unroll
        for (int j = 0; j < 8; j++)
            #pragma unroll
            for (int q = 0; q < 4; q++) acc[i][j][q] = 0.f;

    for (int kt = 0; kt < 8; kt++) {
        // load A chunk: 128 rows x 16 k
        #pragma unroll
        for (int rr = 0; rr < 2; rr++) {
            int q = tid + rr * 256;
            int row = q >> 2, seg = (q & 3) * 4;
            int gr = m0 + row;
            float4 v = make_float4(0.f, 0.f, 0.f, 0.f);
            if (gr < M) v = *reinterpret_cast<const float4*>(A + (size_t)gr * 128 + kt * 16 + seg);
            float vv[4] = {v.x, v.y, v.z, v.w};
            #pragma unroll
            for (int i = 0; i < 4; i++) {
                float hi = f2tf32(vv[i]);
                As[0][row][seg + i] = hi;
                As[1][row][seg + i] = f2tf32(vv[i] - hi);
            }
        }
        // load B chunk: 16 k rows x 128 n
        #pragma unroll
        for (int rr = 0; rr < 2; rr++) {
            int q = tid + rr * 256;
            int row = q >> 5, cc = (q & 31) * 4;
            float4 v = *reinterpret_cast<const float4*>(B + (size_t)(kt * 16 + row) * 128 + cc);
            float vv[4] = {v.x, v.y, v.z, v.w};
            #pragma unroll
            for (int i = 0; i < 4; i++) {
                float hi = f2tf32(vv[i]);
                Bs[0][row][cc + i] = hi;
                Bs[1][row][cc + i] = f2tf32(vv[i] - hi);
            }
        }
        __syncthreads();
        #pragma unroll
        for (int kk = 0; kk < 2; kk++) {
            int k0 = kk * 8;
            uint32_t ah[2][4], alo[2][4];
            #pragma unroll
            for (int i = 0; i < 2; i++) {
                int m = wm * 32 + i * 16;
                ah[i][0]  = __float_as_uint(As[0][m + r    ][k0 + c]);
                ah[i][1]  = __float_as_uint(As[0][m + r + 8][k0 + c]);
                ah[i][2]  = __float_as_uint(As[0][m + r    ][k0 + c + 4]);
                ah[i][3]  = __float_as_uint(As[0][m + r + 8][k0 + c + 4]);
                alo[i][0] = __float_as_uint(As[1][m + r    ][k0 + c]);
                alo[i][1] = __float_as_uint(As[1][m + r + 8][k0 + c]);
                alo[i][2] = __float_as_uint(As[1][m + r    ][k0 + c + 4]);
                alo[i][3] = __float_as_uint(As[1][m + r + 8][k0 + c + 4]);
            }
            #pragma unroll
            for (int j = 0; j < 8; j++) {
                int n = wn * 64 + j * 8 + r;
                uint32_t bh[2], bl[2];
                bh[0] = __float_as_uint(Bs[0][k0 + c][n]);
                bh[1] = __float_as_uint(Bs[0][k0 + c + 4][n]);
                bl[0] = __float_as_uint(Bs[1][k0 + c][n]);
                bl[1] = __float_as_uint(Bs[1][k0 + c + 4][n]);
                #pragma unroll
                for (int i = 0; i < 2; i++) {
                    mma_tf32(acc[i][j], ah[i], bl);
                    mma_tf32(acc[i][j], alo[i], bh);
                    mma_tf32(acc[i][j], ah[i], bh);
                }
            }
        }
        __syncthreads();
    }
    // epilogue
    #pragma unroll
    for (int i = 0; i < 2; i++)
        #pragma unroll
        for (int j = 0; j < 8; j++) {
            int row0 = m0 + wm * 32 + i * 16 + r;
            int col = wn * 64 + j * 8 + c * 2;
            if (row0 < M)
                *reinterpret_cast<float2*>(C + (size_t)row0 * 128 + col) =
                    make_float2(acc[i][j][0], acc[i][j][1]);
            int row1 = row0 + 8;
            if (row1 < M)
                *reinterpret_cast<float2*>(C + (size_t)row1 * 128 + col) =
                    make_float2(acc[i][j][2], acc[i][j][3]);
        }
}

// ---------------- per-edge softmax weights (exp fused, written in CSR order) ----------------
// w[pos[e]][h] = exp(leaky_relu(el[src,h] + er[dst,h] + Ef[e]@Wae[:,h]))
__global__ __launch_bounds__(128) void edge_score_kernel(const float* __restrict__ Ef,
                                                         const int* __restrict__ src,
                                                         const int* __restrict__ dst,
                                                         const float* __restrict__ el,
                                                         const float* __restrict__ er,
                                                         const float* __restrict__ Wae,
                                                         const int* __restrict__ pos,
                                                         float4* __restrict__ wout, int E) {
    __shared__ float w[64];
    if (threadIdx.x < 64) w[threadIdx.x] = Wae[threadIdx.x];
    __syncthreads();
    int e = blockIdx.x * blockDim.x + threadIdx.x;
    if (e >= E) return;
    int s = src[e], d = dst[e], p = pos[e];
    float4 el4 = reinterpret_cast<const float4*>(el)[s];
    float4 er4 = reinterpret_cast<const float4*>(er)[d];
    const float4* efp = reinterpret_cast<const float4*>(Ef + (size_t)e * 16);
    float4 v0 = efp[0], v1 = efp[1], v2 = efp[2], v3 = efp[3];
    float ef[16] = {v0.x, v0.y, v0.z, v0.w, v1.x, v1.y, v1.z, v1.w,
                    v2.x, v2.y, v2.z, v2.w, v3.x, v3.y, v3.z, v3.w};
    float base[4] = {el4.x + er4.x, el4.y + er4.y, el4.z + er4.z, el4.w + er4.w};
    float o[4];
    #pragma unroll
    for (int h = 0; h < 4; h++) {
        float acc = base[h];
        #pragma unroll
        for (int f = 0; f < 16; f++) acc = fmaf(ef[f], w[f * 4 + h], acc);
        acc = acc > 0.f ? acc : 0.2f * acc;
        o[h] = __expf(acc);
    }
    wout[p] = make_float4(o[0], o[1], o[2], o[3]);
}

// ---------------- single-pass softmax aggregation (one block per dst node) ----------------
__global__ __launch_bounds__(128) void aggregate_kernel(const int* __restrict__ indptr,
                                                        const int* __restrict__ srcp,
                                                        const float4* __restrict__ w,
                                                        const float* __restrict__ fs,
                                                        float* __restrict__ out,
                                                        int N, int do_relu) {
    __shared__ float4 sw[128];
    __shared__ int ss[128];
    int n = blockIdx.x;
    int beg = indptr[n], end = indptr[n + 1];
    int t = threadIdx.x;
    int h = t >> 5;
    float s = 0.f, acc = 0.f;
    for (int cs = beg; cs < end; cs += 128) {
        int cnt = min(128, end - cs);
        if (t < cnt) { sw[t] = w[cs + t]; ss[t] = srcp[cs + t]; }
        __syncthreads();
        for (int j = 0; j < cnt; j++) {
            float wv = reinterpret_cast<const float*>(&sw[j])[h];
            s += wv;
            acc = fmaf(wv, fs[(size_t)ss[j] * 128 + t], acc);
        }
        __syncthreads();
    }
    float o = acc / (s + 1e-9f);
    if (do_relu) o = fmaxf(o, 0.f);
    out[(size_t)n * 128 + t] = o;
}

// ---------------- host orchestration ----------------
static void build_csr(const int* dst, const int* src, int E, int N,
                      int* indptr, int* pos, int* srcp, int* cnt, int* cur) {
    fill_int_kernel<<<(N + 255) / 256, 256>>>(cnt, 0, N);
    hist_kernel<<<(E + 255) / 256, 256>>>(dst, cnt, E);
    scan_kernel<<<1, 1024>>>(cnt, indptr, N);
    copy_int_kernel<<<(N + 255) / 256, 256>>>(cur, indptr, N);
    scatter_kernel<<<(E + 255) / 256, 256>>>(dst, src, cur, pos, srcp, E);
}

extern "C" void kernel_launch(void* const* d_in, const int* in_sizes, int n_in,
                              void* d_out, int out_size) {
    const float* X_user = (const float*)d_in[0];
    const float* X_item = (const float*)d_in[1];
    const float* Ef_ui0 = (const float*)d_in[2];
    const float* Ef_iu0 = (const float*)d_in[3];
    const float* Ef_ui1 = (const float*)d_in[4];
    const float* Ef_iu1 = (const float*)d_in[5];
    const float* Wt[4][5];
    for (int g = 0; g < 4; g++)
        for (int k = 0; k < 5; k++)
            Wt[g][k] = (const float*)d_in[6 + g * 5 + k];
    const int* src_ui = (const int*)d_in[26];
    const int* dst_ui = (const int*)d_in[27];
    const int* src_iu = (const int*)d_in[28];
    const int* dst_iu = (const int*)d_in[29];

    const int NU = in_sizes[0] / 128;
    const int NI = in_sizes[1] / 128;
    const int E_ui = in_sizes[26];
    const int E_iu = in_sizes[28];

    float *hu1, *hi1, *fs, *el_ui, *er_ui, *el_iu, *er_iu, *wbuf, *wl, *wr, *wae;
    int *ip_ui, *ip_iu, *pos_ui, *pos_iu, *srcp_ui, *srcp_iu, *cnt, *cur;
    cudaGetSymbolAddress((void**)&hu1, g_hu1);
    cudaGetSymbolAddress((void**)&hi1, g_hi1);
    cudaGetSymbolAddress((void**)&fs, g_fs);
    cudaGetSymbolAddress((void**)&el_ui, g_el_ui);
    cudaGetSymbolAddress((void**)&er_ui, g_er_ui);
    cudaGetSymbolAddress((void**)&el_iu, g_el_iu);
    cudaGetSymbolAddress((void**)&er_iu, g_er_iu);
    cudaGetSymbolAddress((void**)&wbuf, g_w);
    cudaGetSymbolAddress((void**)&wl, g_wl);
    cudaGetSymbolAddress((void**)&wr, g_wr);
    cudaGetSymbolAddress((void**)&wae, g_wae);
    cudaGetSymbolAddress((void**)&ip_ui, g_ip_ui);
    cudaGetSymbolAddress((void**)&ip_iu, g_ip_iu);
    cudaGetSymbolAddress((void**)&pos_ui, g_pos_ui);
    cudaGetSymbolAddress((void**)&pos_iu, g_pos_iu);
    cudaGetSymbolAddress((void**)&srcp_ui, g_srcp_ui);
    cudaGetSymbolAddress((void**)&srcp_iu, g_srcp_iu);
    cudaGetSymbolAddress((void**)&cnt, g_cnt);
    cudaGetSymbolAddress((void**)&cur, g_cur);

    float* out_hu2 = (float*)d_out;
    float* out_hi2 = (float*)d_out + (size_t)NU * 128;

    // reduced attention weights for all 4 groups, one launch
    RW p;
    for (int g = 0; g < 4; g++) {
        p.W[g] = Wt[g][0]; p.We[g] = Wt[g][1];
        p.al[g] = Wt[g][2]; p.ar[g] = Wt[g][3]; p.ae[g] = Wt[g][4];
    }
    p.wl = wl; p.wr = wr; p.wae = wae;
    reduce_all_kernel<<<12, 128>>>(p);

    // CSR (reused by both layers)
    build_csr(dst_ui, src_ui, E_ui, NI, ip_ui, pos_ui, srcp_ui, cnt, cur);
    build_csr(dst_iu, src_iu, E_iu, NU, ip_iu, pos_iu, srcp_iu, cnt, cur);

    float4* w4 = (float4*)wbuf;

    // ---- layer 0 ----
    attn_proj2_kernel<<<(NU + 3) / 4, 128>>>(X_user, wl + 0 * 512, wr + 1 * 512, el_ui, er_iu, NU);
    attn_proj2_kernel<<<(NI + 3) / 4, 128>>>(X_item, wl + 1 * 512, wr + 0 * 512, el_iu, er_ui, NI);

    gemm3t_kernel<<<(NU + 127) / 128, 256>>>(X_user, Wt[0][0], fs, NU);
    edge_score_kernel<<<(E_ui + 127) / 128, 128>>>(Ef_ui0, src_ui, dst_ui, el_ui, er_ui,
                                                   wae + 0 * 64, pos_ui, w4, E_ui);
    aggregate_kernel<<<NI, 128>>>(ip_ui, srcp_ui, w4, fs, hi1, NI, 1);

    gemm3t_kernel<<<(NI + 127) / 128, 256>>>(X_item, Wt[1][0], fs, NI);
    edge_score_kernel<<<(E_iu + 127) / 128, 128>>>(Ef_iu0, src_iu, dst_iu, el_iu, er_iu,
                                                   wae + 1 * 64, pos_iu, w4, E_iu);
    aggregate_kernel<<<NU, 128>>>(ip_iu, srcp_iu, w4, fs, hu1, NU, 1);

    // ---- layer 1 ----
    attn_proj2_kernel<<<(NU + 3) / 4, 128>>>(hu1, wl + 2 * 512, wr + 3 * 512, el_ui, er_iu, NU);
    attn_proj2_kernel<<<(NI + 3) / 4, 128>>>(hi1, wl + 3 * 512, wr + 2 * 512, el_iu, er_ui, NI);

    gemm3t_kernel<<<(NU + 127) / 128, 256>>>(hu1, Wt[2][0], fs, NU);
    edge_score_kernel<<<(E_ui + 127) / 128, 128>>>(Ef_ui1, src_ui, dst_ui, el_ui, er_ui,
                                                   wae + 2 * 64, pos_ui, w4, E_ui);
    aggregate_kernel<<<NI, 128>>>(ip_ui, srcp_ui, w4, fs, out_hi2, NI, 0);

    gemm3t_kernel<<<(NI + 127) / 128, 256>>>(hi1, Wt[3][0], fs, NI);
    edge_score_kernel<<<(E_iu + 127) / 128, 128>>>(Ef_iu1, src_iu, dst_iu, el_iu, er_iu,
                                                   wae + 3 * 64, pos_iu, w4, E_iu);
    aggregate_kernel<<<NU, 128>>>(ip_iu, srcp_iu, w4, fs, out_hu2, NU, 0);
}

// round 4
// speedup vs baseline: 1.5521x; 1.1706x over previous
#include <cuda_runtime.h>
#include <math.h>
#include <stdint.h>

#define NMAX 50000
#define EMAX 500000

// ---------------- scratch (static device globals) ----------------
__device__ float g_hu1[NMAX * 128];
__device__ float g_hi1[NMAX * 128];
__device__ float g_fs [NMAX * 128];
__device__ float g_fs2[NMAX * 128];
__device__ float g_el_ui[NMAX * 4];
__device__ float g_er_ui[NMAX * 4];
__device__ float g_el_iu[NMAX * 4];
__device__ float g_er_iu[NMAX * 4];
__device__ float g_w  [EMAX * 4];
__device__ float g_wl [4][512];
__device__ float g_wr [4][512];
__device__ float g_wae[4][64];
__device__ int   g_ip_ui[NMAX + 1];
__device__ int   g_ip_iu[NMAX + 1];
__device__ int   g_pos_ui[EMAX];
__device__ int   g_pos_iu[EMAX];
__device__ int   g_srcp_ui[EMAX];
__device__ int   g_srcp_iu[EMAX];
__device__ int   g_cnt[2 * NMAX];
__device__ int   g_cur[2 * NMAX];

// ---------------- CSR build (4 launches total for both directions) ----------------
__global__ void fill0_kernel(int* p, int n) {
    int i = blockIdx.x * blockDim.x + threadIdx.x;
    if (i < n) p[i] = 0;
}
__global__ void hist2_kernel(const int* __restrict__ d0, const int* __restrict__ d1,
                             int* cnt0, int* cnt1, int E0, int E1) {
    int i = blockIdx.x * blockDim.x + threadIdx.x;
    if (i < E0) atomicAdd(&cnt0[d0[i]], 1);
    else if (i < E0 + E1) atomicAdd(&cnt1[d1[i - E0]], 1);
}
// two-block scan: block b scans cnt[b] -> indptr[b] (size n+1) and cur[b] (exclusive)
struct ScanArgs {
    const int* cnt[2]; int* indptr[2]; int* cur[2]; int n[2];
};
__global__ __launch_bounds__(1024) void scan2_kernel(ScanArgs a) {
    __shared__ int warp_sums[32];
    int b = blockIdx.x;
    const int* cnt = a.cnt[b];
    int* indptr = a.indptr[b];
    int* cur = a.cur[b];
    int n = a.n[b];
    int tid = threadIdx.x, lane = tid & 31, warp = tid >> 5;
    int chunk = (n + 1023) >> 10;
    int lo = min(tid * chunk, n), hi = min(lo + chunk, n);
    int sum = 0;
    for (int i = lo; i < hi; i++) sum += cnt[i];
    // exclusive scan of per-thread sums
    int x = sum;
    #pragma unroll
    for (int o = 1; o < 32; o <<= 1) {
        int y = __shfl_up_sync(0xffffffffu, x, o);
        if (lane >= o) x += y;
    }
    if (lane == 31) warp_sums[warp] = x;
    __syncthreads();
    if (warp == 0) {
        int s = warp_sums[lane];
        #pragma unroll
        for (int o = 1; o < 32; o <<= 1) {
            int y = __shfl_up_sync(0xffffffffu, s, o);
            if (lane >= o) s += y;
        }
        warp_sums[lane] = s;
    }
    __syncthreads();
    int run = x - sum + (warp > 0 ? warp_sums[warp - 1] : 0);  // exclusive prefix
    if (tid == 0) indptr[0] = 0;
    for (int i = lo; i < hi; i++) {
        cur[i] = run;
        run += cnt[i];
        indptr[i + 1] = run;
    }
}
__global__ void scatter2_kernel(const int* __restrict__ d0, const int* __restrict__ s0,
                                const int* __restrict__ d1, const int* __restrict__ s1,
                                int* cur0, int* cur1,
                                int* pos0, int* srcp0, int* pos1, int* srcp1,
                                int E0, int E1) {
    int i = blockIdx.x * blockDim.x + threadIdx.x;
    if (i < E0) {
        int p = atomicAdd(&cur0[d0[i]], 1);
        pos0[i] = p;
        srcp0[p] = s0[i];
    } else if (i < E0 + E1) {
        int j = i - E0;
        int p = atomicAdd(&cur1[d1[j]], 1);
        pos1[j] = p;
        srcp1[p] = s1[j];
    }
}

// ---------------- reduced attention weights (all 4 groups, one launch) ----------------
struct RW {
    const float* W[4];  const float* We[4];
    const float* al[4]; const float* ar[4]; const float* ae[4];
    float* wl; float* wr; float* wae;
};
__global__ void reduce_all_kernel(RW p) {
    int g = blockIdx.x / 3;
    int which = blockIdx.x % 3;
    int f = threadIdx.x;
    if (which == 2) {
        if (f >= 16) return;
        const float* We = p.We[g];
        const float* ae = p.ae[g];
        #pragma unroll
        for (int h = 0; h < 4; h++) {
            float s = 0.f;
            #pragma unroll
            for (int d = 0; d < 32; d++) s = fmaf(We[f * 128 + h * 32 + d], ae[h * 32 + d], s);
            p.wae[g * 64 + f * 4 + h] = s;
        }
    } else {
        const float* W = p.W[g];
        const float* a = which ? p.ar[g] : p.al[g];
        float* o = (which ? p.wr : p.wl) + g * 512;
        #pragma unroll
        for (int h = 0; h < 4; h++) {
            float s = 0.f;
            #pragma unroll
            for (int d = 0; d < 32; d++) s = fmaf(W[f * 128 + h * 32 + d], a[h * 32 + d], s);
            o[f * 4 + h] = s;
        }
    }
}

// ---------------- dual attention projection: outA = X@wA, outB = X@wB ----------------
__global__ __launch_bounds__(128) void attn_proj2_kernel(const float* __restrict__ X,
                                                         const float* __restrict__ wA,
                                                         const float* __restrict__ wB,
                                                         float* __restrict__ outA,
                                                         float* __restrict__ outB, int N) {
    __shared__ float wa[512], wb[512];
    int tid = threadIdx.x;
    #pragma unroll
    for (int i = tid; i < 512; i += 128) { wa[i] = wA[i]; wb[i] = wB[i]; }
    __syncthreads();
    int warp = tid >> 5, lane = tid & 31;
    int n = blockIdx.x * 4 + warp;
    if (n >= N) return;
    float a[4] = {0, 0, 0, 0}, b[4] = {0, 0, 0, 0};
    #pragma unroll
    for (int r = 0; r < 4; r++) {
        int f = lane + r * 32;
        float x = X[(size_t)n * 128 + f];
        #pragma unroll
        for (int h = 0; h < 4; h++) {
            a[h] = fmaf(x, wa[f * 4 + h], a[h]);
            b[h] = fmaf(x, wb[f * 4 + h], b[h]);
        }
    }
    #pragma unroll
    for (int o = 16; o; o >>= 1)
        #pragma unroll
        for (int h = 0; h < 4; h++) {
            a[h] += __shfl_down_sync(0xffffffffu, a[h], o);
            b[h] += __shfl_down_sync(0xffffffffu, b[h], o);
        }
    if (lane == 0) {
        #pragma unroll
        for (int h = 0; h < 4; h++) { outA[n * 4 + h] = a[h]; outB[n * 4 + h] = b[h]; }
    }
}

// ---------------- 3xTF32 tensor-core GEMM (paired: two problems in one launch) ----------------
__device__ __forceinline__ float f2tf32(float x) {
    uint32_t u;
    asm("cvt.rna.tf32.f32 %0, %1;" : "=r"(u) : "f"(x));
    return __uint_as_float(u);
}
__device__ __forceinline__ void mma_tf32(float* d, const uint32_t* a, const uint32_t* b) {
    asm volatile("mma.sync.aligned.m16n8k8.row.col.f32.tf32.tf32.f32 "
                 "{%0,%1,%2,%3}, {%4,%5,%6,%7}, {%8,%9}, {%0,%1,%2,%3};\n"
                 : "+f"(d[0]), "+f"(d[1]), "+f"(d[2]), "+f"(d[3])
                 : "r"(a[0]), "r"(a[1]), "r"(a[2]), "r"(a[3]), "r"(b[0]), "r"(b[1]));
}

__global__ __launch_bounds__(256, 2) void gemm3t2_kernel(const float* __restrict__ A0,
                                                         const float* __restrict__ B0,
                                                         float* __restrict__ C0, int M0, int NB0,
                                                         const float* __restrict__ A1,
                                                         const float* __restrict__ B1,
                                                         float* __restrict__ C1, int M1) {
    __shared__ float As[2][128][20];
    __shared__ float Bs[2][16][136];
    const float* A; const float* B; float* C; int M, bx;
    if ((int)blockIdx.x < NB0) { A = A0; B = B0; C = C0; M = M0; bx = blockIdx.x; }
    else                       { A = A1; B = B1; C = C1; M = M1; bx = blockIdx.x - NB0; }
    const int tid = threadIdx.x;
    const int lane = tid & 31, wid = tid >> 5;
    const int wm = wid & 3, wn = wid >> 2;
    const int m0 = bx * 128;
    const int r = lane >> 2, c = lane & 3;

    float acc[2][8][4];
    #pragma unroll
    for (int i = 0; i < 2; i++)
        #pragma unroll
        for (int j = 0; j < 8; j++)
            #pragma unroll
            for (int q = 0; q < 4; q++) acc[i][j][q] = 0.f;

    for (int kt = 0; kt < 8; kt++) {
        #pragma unroll
        for (int rr = 0; rr < 2; rr++) {
            int q = tid + rr * 256;
            int row = q >> 2, seg = (q & 3) * 4;
            int gr = m0 + row;
            float4 v = make_float4(0.f, 0.f, 0.f, 0.f);
            if (gr < M) v = *reinterpret_cast<const float4*>(A + (size_t)gr * 128 + kt * 16 + seg);
            float vv[4] = {v.x, v.y, v.z, v.w};
            #pragma unroll
            for (int i = 0; i < 4; i++) {
                float hi = f2tf32(vv[i]);
                As[0][row][seg + i] = hi;
                As[1][row][seg + i] = f2tf32(vv[i] - hi);
            }
        }
        #pragma unroll
        for (int rr = 0; rr < 2; rr++) {
            int q = tid + rr * 256;
            int row = q >> 5, cc = (q & 31) * 4;
            float4 v = *reinterpret_cast<const float4*>(B + (size_t)(kt * 16 + row) * 128 + cc);
            float vv[4] = {v.x, v.y, v.z, v.w};
            #pragma unroll
            for (int i = 0; i < 4; i++) {
                float hi = f2tf32(vv[i]);
                Bs[0][row][cc + i] = hi;
                Bs[1][row][cc + i] = f2tf32(vv[i] - hi);
            }
        }
        __syncthreads();
        #pragma unroll
        for (int kk = 0; kk < 2; kk++) {
            int k0 = kk * 8;
            uint32_t ah[2][4], alo[2][4];
            #pragma unroll
            for (int i = 0; i < 2; i++) {
                int m = wm * 32 + i * 16;
                ah[i][0]  = __float_as_uint(As[0][m + r    ][k0 + c]);
                ah[i][1]  = __float_as_uint(As[0][m + r + 8][k0 + c]);
                ah[i][2]  = __float_as_uint(As[0][m + r    ][k0 + c + 4]);
                ah[i][3]  = __float_as_uint(As[0][m + r + 8][k0 + c + 4]);
                alo[i][0] = __float_as_uint(As[1][m + r    ][k0 + c]);
                alo[i][1] = __float_as_uint(As[1][m + r + 8][k0 + c]);
                alo[i][2] = __float_as_uint(As[1][m + r    ][k0 + c + 4]);
                alo[i][3] = __float_as_uint(As[1][m + r + 8][k0 + c + 4]);
            }
            #pragma unroll
            for (int j = 0; j < 8; j++) {
                int n = wn * 64 + j * 8 + r;
                uint32_t bh[2], bl[2];
                bh[0] = __float_as_uint(Bs[0][k0 + c][n]);
                bh[1] = __float_as_uint(Bs[0][k0 + c + 4][n]);
                bl[0] = __float_as_uint(Bs[1][k0 + c][n]);
                bl[1] = __float_as_uint(Bs[1][k0 + c + 4][n]);
                #pragma unroll
                for (int i = 0; i < 2; i++) {
                    mma_tf32(acc[i][j], ah[i], bl);
                    mma_tf32(acc[i][j], alo[i], bh);
                    mma_tf32(acc[i][j], ah[i], bh);
                }
            }
        }
        __syncthreads();
    }
    #pragma unroll
    for (int i = 0; i < 2; i++)
        #pragma unroll
        for (int j = 0; j < 8; j++) {
            int row0 = m0 + wm * 32 + i * 16 + r;
            int col = wn * 64 + j * 8 + c * 2;
            if (row0 < M)
                *reinterpret_cast<float2*>(C + (size_t)row0 * 128 + col) =
                    make_float2(acc[i][j][0], acc[i][j][1]);
            int row1 = row0 + 8;
            if (row1 < M)
                *reinterpret_cast<float2*>(C + (size_t)row1 * 128 + col) =
                    make_float2(acc[i][j][2], acc[i][j][3]);
        }
}

// ---------------- per-edge softmax weights (exp fused, written in CSR order) ----------------
__global__ __launch_bounds__(128) void edge_score_kernel(const float* __restrict__ Ef,
                                                         const int* __restrict__ src,
                                                         const int* __restrict__ dst,
                                                         const float* __restrict__ el,
                                                         const float* __restrict__ er,
                                                         const float* __restrict__ Wae,
                                                         const int* __restrict__ pos,
                                                         float4* __restrict__ wout, int E) {
    __shared__ float w[64];
    if (threadIdx.x < 64) w[threadIdx.x] = Wae[threadIdx.x];
    __syncthreads();
    int e = blockIdx.x * blockDim.x + threadIdx.x;
    if (e >= E) return;
    int s = src[e], d = dst[e], p = pos[e];
    float4 el4 = reinterpret_cast<const float4*>(el)[s];
    float4 er4 = reinterpret_cast<const float4*>(er)[d];
    const float4* efp = reinterpret_cast<const float4*>(Ef + (size_t)e * 16);
    float4 v0 = efp[0], v1 = efp[1], v2 = efp[2], v3 = efp[3];
    float ef[16] = {v0.x, v0.y, v0.z, v0.w, v1.x, v1.y, v1.z, v1.w,
                    v2.x, v2.y, v2.z, v2.w, v3.x, v3.y, v3.z, v3.w};
    float base[4] = {el4.x + er4.x, el4.y + er4.y, el4.z + er4.z, el4.w + er4.w};
    float o[4];
    #pragma unroll
    for (int h = 0; h < 4; h++) {
        float acc = base[h];
        #pragma unroll
        for (int f = 0; f < 16; f++) acc = fmaf(ef[f], w[f * 4 + h], acc);
        acc = acc > 0.f ? acc : 0.2f * acc;
        o[h] = __expf(acc);
    }
    wout[p] = make_float4(o[0], o[1], o[2], o[3]);
}

// ---------------- warp-per-node softmax aggregation ----------------
__global__ __launch_bounds__(256) void aggregate_kernel(const int* __restrict__ indptr,
                                                        const int* __restrict__ srcp,
                                                        const float* __restrict__ wf,
                                                        const float4* __restrict__ fs4,
                                                        float4* __restrict__ out4,
                                                        int N, int do_relu) {
    int gw = (blockIdx.x * 256 + threadIdx.x) >> 5;  // node id
    if (gw >= N) return;
    int lane = threadIdx.x & 31;
    int h = lane >> 3;
    int beg = indptr[gw], end = indptr[gw + 1];
    float4 acc0 = make_float4(0.f, 0.f, 0.f, 0.f);
    float4 acc1 = make_float4(0.f, 0.f, 0.f, 0.f);
    float s0 = 0.f, s1 = 0.f;
    int j = beg;
    for (; j + 2 <= end; j += 2) {
        int sa = srcp[j], sb = srcp[j + 1];
        float wa = wf[j * 4 + h], wb = wf[(j + 1) * 4 + h];
        float4 va = fs4[(size_t)sa * 32 + lane];
        float4 vb = fs4[(size_t)sb * 32 + lane];
        acc0.x = fmaf(wa, va.x, acc0.x); acc0.y = fmaf(wa, va.y, acc0.y);
        acc0.z = fmaf(wa, va.z, acc0.z); acc0.w = fmaf(wa, va.w, acc0.w);
        s0 += wa;
        acc1.x = fmaf(wb, vb.x, acc1.x); acc1.y = fmaf(wb, vb.y, acc1.y);
        acc1.z = fmaf(wb, vb.z, acc1.z); acc1.w = fmaf(wb, vb.w, acc1.w);
        s1 += wb;
    }
    if (j < end) {
        int sa = srcp[j];
        float wa = wf[j * 4 + h];
        float4 va = fs4[(size_t)sa * 32 + lane];
        acc0.x = fmaf(wa, va.x, acc0.x); acc0.y = fmaf(wa, va.y, acc0.y);
        acc0.z = fmaf(wa, va.z, acc0.z); acc0.w = fmaf(wa, va.w, acc0.w);
        s0 += wa;
    }
    float inv = 1.f / (s0 + s1 + 1e-9f);
    float4 o = make_float4((acc0.x + acc1.x) * inv, (acc0.y + acc1.y) * inv,
                           (acc0.z + acc1.z) * inv, (acc0.w + acc1.w) * inv);
    if (do_relu) {
        o.x = fmaxf(o.x, 0.f); o.y = fmaxf(o.y, 0.f);
        o.z = fmaxf(o.z, 0.f); o.w = fmaxf(o.w, 0.f);
    }
    out4[(size_t)gw * 32 + lane] = o;
}

// ---------------- host orchestration ----------------
extern "C" void kernel_launch(void* const* d_in, const int* in_sizes, int n_in,
                              void* d_out, int out_size) {
    const float* X_user = (const float*)d_in[0];
    const float* X_item = (const float*)d_in[1];
    const float* Ef_ui0 = (const float*)d_in[2];
    const float* Ef_iu0 = (const float*)d_in[3];
    const float* Ef_ui1 = (const float*)d_in[4];
    const float* Ef_iu1 = (const float*)d_in[5];
    const float* Wt[4][5];
    for (int g = 0; g < 4; g++)
        for (int k = 0; k < 5; k++)
            Wt[g][k] = (const float*)d_in[6 + g * 5 + k];
    const int* src_ui = (const int*)d_in[26];
    const int* dst_ui = (const int*)d_in[27];
    const int* src_iu = (const int*)d_in[28];
    const int* dst_iu = (const int*)d_in[29];

    const int NU = in_sizes[0] / 128;
    const int NI = in_sizes[1] / 128;
    const int E_ui = in_sizes[26];
    const int E_iu = in_sizes[28];

    float *hu1, *hi1, *fs, *fs2, *el_ui, *er_ui, *el_iu, *er_iu, *wbuf, *wl, *wr, *wae;
    int *ip_ui, *ip_iu, *pos_ui, *pos_iu, *srcp_ui, *srcp_iu, *cnt, *cur;
    cudaGetSymbolAddress((void**)&hu1, g_hu1);
    cudaGetSymbolAddress((void**)&hi1, g_hi1);
    cudaGetSymbolAddress((void**)&fs, g_fs);
    cudaGetSymbolAddress((void**)&fs2, g_fs2);
    cudaGetSymbolAddress((void**)&el_ui, g_el_ui);
    cudaGetSymbolAddress((void**)&er_ui, g_er_ui);
    cudaGetSymbolAddress((void**)&el_iu, g_el_iu);
    cudaGetSymbolAddress((void**)&er_iu, g_er_iu);
    cudaGetSymbolAddress((void**)&wbuf, g_w);
    cudaGetSymbolAddress((void**)&wl, g_wl);
    cudaGetSymbolAddress((void**)&wr, g_wr);
    cudaGetSymbolAddress((void**)&wae, g_wae);
    cudaGetSymbolAddress((void**)&ip_ui, g_ip_ui);
    cudaGetSymbolAddress((void**)&ip_iu, g_ip_iu);
    cudaGetSymbolAddress((void**)&pos_ui, g_pos_ui);
    cudaGetSymbolAddress((void**)&pos_iu, g_pos_iu);
    cudaGetSymbolAddress((void**)&srcp_ui, g_srcp_ui);
    cudaGetSymbolAddress((void**)&srcp_iu, g_srcp_iu);
    cudaGetSymbolAddress((void**)&cnt, g_cnt);
    cudaGetSymbolAddress((void**)&cur, g_cur);

    float* out_hu2 = (float*)d_out;
    float* out_hi2 = (float*)d_out + (size_t)NU * 128;

    RW p;
    for (int g = 0; g < 4; g++) {
        p.W[g] = Wt[g][0]; p.We[g] = Wt[g][1];
        p.al[g] = Wt[g][2]; p.ar[g] = Wt[g][3]; p.ae[g] = Wt[g][4];
    }
    p.wl = wl; p.wr = wr; p.wae = wae;
    reduce_all_kernel<<<12, 128>>>(p);

    // ---- CSR build (both directions, 4 launches) ----
    int* cnt_ui = cnt;           int* cnt_iu = cnt + NMAX;
    int* cur_ui = cur;           int* cur_iu = cur + NMAX;
    fill0_kernel<<<(2 * NMAX + 255) / 256, 256>>>(cnt, 2 * NMAX);
    hist2_kernel<<<(E_ui + E_iu + 255) / 256, 256>>>(dst_ui, dst_iu, cnt_ui, cnt_iu, E_ui, E_iu);
    ScanArgs sa;
    sa.cnt[0] = cnt_ui; sa.indptr[0] = ip_ui; sa.cur[0] = cur_ui; sa.n[0] = NI;
    sa.cnt[1] = cnt_iu; sa.indptr[1] = ip_iu; sa.cur[1] = cur_iu; sa.n[1] = NU;
    scan2_kernel<<<2, 1024>>>(sa);
    scatter2_kernel<<<(E_ui + E_iu + 255) / 256, 256>>>(dst_ui, src_ui, dst_iu, src_iu,
                                                        cur_ui, cur_iu,
                                                        pos_ui, srcp_ui, pos_iu, srcp_iu,
                                                        E_ui, E_iu);

    float4* w4 = (float4*)wbuf;
    int nb_u = (NU + 127) / 128, nb_i = (NI + 127) / 128;

    // ---- layer 0 ----
    attn_proj2_kernel<<<(NU + 3) / 4, 128>>>(X_user, wl + 0 * 512, wr + 1 * 512, el_ui, er_iu, NU);
    attn_proj2_kernel<<<(NI + 3) / 4, 128>>>(X_item, wl + 1 * 512, wr + 0 * 512, el_iu, er_ui, NI);

    gemm3t2_kernel<<<nb_u + nb_i, 256>>>(X_user, Wt[0][0], fs, NU, nb_u,
                                         X_item, Wt[1][0], fs2, NI);
    edge_score_kernel<<<(E_ui + 127) / 128, 128>>>(Ef_ui0, src_ui, dst_ui, el_ui, er_ui,
                                                   wae + 0 * 64, pos_ui, w4, E_ui);
    aggregate_kernel<<<(NI * 32 + 255) / 256, 256>>>(ip_ui, srcp_ui, wbuf, (const float4*)fs,
                                                     (float4*)hi1, NI, 1);
    edge_score_kernel<<<(E_iu + 127) / 128, 128>>>(Ef_iu0, src_iu, dst_iu, el_iu, er_iu,
                                                   wae + 1 * 64, pos_iu, w4, E_iu);
    aggregate_kernel<<<(NU * 32 + 255) / 256, 256>>>(ip_iu, srcp_iu, wbuf, (const float4*)fs2,
                                                     (float4*)hu1, NU, 1);

    // ---- layer 1 ----
    attn_proj2_kernel<<<(NU + 3) / 4, 128>>>(hu1, wl + 2 * 512, wr + 3 * 512, el_ui, er_iu, NU);
    attn_proj2_kernel<<<(NI + 3) / 4, 128>>>(hi1, wl + 3 * 512, wr + 2 * 512, el_iu, er_ui, NI);

    gemm3t2_kernel<<<nb_u + nb_i, 256>>>(hu1, Wt[2][0], fs, NU, nb_u,
                                         hi1, Wt[3][0], fs2, NI);
    edge_score_kernel<<<(E_ui + 127) / 128, 128>>>(Ef_ui1, src_ui, dst_ui, el_ui, er_ui,
                                                   wae + 2 * 64, pos_ui, w4, E_ui);
    aggregate_kernel<<<(NI * 32 + 255) / 256, 256>>>(ip_ui, srcp_ui, wbuf, (const float4*)fs,
                                                     (float4*)out_hi2, NI, 0);
    edge_score_kernel<<<(E_iu + 127) / 128, 128>>>(Ef_iu1, src_iu, dst_iu, el_iu, er_iu,
                                                   wae + 3 * 64, pos_iu, w4, E_iu);
    aggregate_kernel<<<(NU * 32 + 255) / 256, 256>>>(ip_iu, srcp_iu, wbuf, (const float4*)fs2,
                                                     (float4*)out_hu2, NU, 0);
}